// round 11
// baseline (speedup 1.0000x reference)
#include <cuda_runtime.h>
#include <cuda_bf16.h>

#define HIDDEN 128
#define MAX_NODES 131072

__device__ float g_s1[MAX_NODES];
__device__ float g_s2[MAX_NODES];

// Two nodes per warp: lane l loads x[2w][4l..] and x[2w+1][4l..] back-to-back
// (MLP=2), computes 4 partial dots, 4 independent shfl-reduction chains.
// (Measured-best node_dot shape: R5 config, plain loads.)
__global__ __launch_bounds__(256)
void node_dot_kernel(const float4* __restrict__ x4,
                     const float4* __restrict__ W4,
                     int n_nodes,
                     float* __restrict__ s1,
                     float* __restrict__ s2) {
    int warp = (blockIdx.x * blockDim.x + threadIdx.x) >> 5;
    int lane = threadIdx.x & 31;
    int n0 = warp * 2;
    if (n0 >= n_nodes) return;

    float4 w1 = W4[lane];        // W[0:128]   (L1/L2 resident)
    float4 w2 = W4[32 + lane];   // W[128:256]

    // Front-batch both row loads
    const float4* p = x4 + (size_t)n0 * 32 + lane;
    float4 v0 = p[0];
    float4 v1;
    bool has1 = (n0 + 1) < n_nodes;
    if (has1) v1 = p[32];

    float a0 = v0.x * w1.x + v0.y * w1.y + v0.z * w1.z + v0.w * w1.w;
    float c0 = v0.x * w2.x + v0.y * w2.y + v0.z * w2.z + v0.w * w2.w;
    float a1 = 0.f, c1 = 0.f;
    if (has1) {
        a1 = v1.x * w1.x + v1.y * w1.y + v1.z * w1.z + v1.w * w1.w;
        c1 = v1.x * w2.x + v1.y * w2.y + v1.z * w2.z + v1.w * w2.w;
    }

    #pragma unroll
    for (int o = 16; o > 0; o >>= 1) {
        a0 += __shfl_xor_sync(0xFFFFFFFFu, a0, o);
        c0 += __shfl_xor_sync(0xFFFFFFFFu, c0, o);
        a1 += __shfl_xor_sync(0xFFFFFFFFu, a1, o);
        c1 += __shfl_xor_sync(0xFFFFFFFFu, c1, o);
    }
    if (lane == 0) {
        s1[n0] = a0;
        s2[n0] = c0;
        if (has1) {
            s1[n0 + 1] = a1;
            s2[n0 + 1] = c1;
        }
    }
}

// out[e] = s1[src[e]] + s2[dst[e]] + b.
// Measured-best edge shape: 4 edges/thread, int4 index loads, 8 front-batched
// gathers, 128-thread blocks (grid 1563, occ ~51%). At the L1tex
// divergent-gather wavefront floor.
__global__ __launch_bounds__(128)
void edge_kernel(const int* __restrict__ ei,
                 int n_edges,
                 const float* __restrict__ s1,
                 const float* __restrict__ s2,
                 const float* __restrict__ bptr,
                 float* __restrict__ out) {
    float b = __ldg(bptr);
    int tid = blockIdx.x * blockDim.x + threadIdx.x;
    int base = tid * 4;
    const int* src = ei;
    const int* dst = ei + n_edges;

    if (base + 3 < n_edges) {
        int4 s4 = __ldg((const int4*)(src + base));
        int4 d4 = __ldg((const int4*)(dst + base));

        float v0 = __ldg(&s1[s4.x]);
        float v1 = __ldg(&s1[s4.y]);
        float v2 = __ldg(&s1[s4.z]);
        float v3 = __ldg(&s1[s4.w]);
        float u0 = __ldg(&s2[d4.x]);
        float u1 = __ldg(&s2[d4.y]);
        float u2 = __ldg(&s2[d4.z]);
        float u3 = __ldg(&s2[d4.w]);

        float4 r = make_float4(v0 + u0 + b, v1 + u1 + b,
                               v2 + u2 + b, v3 + u3 + b);
        *(float4*)(out + base) = r;
    } else {
        for (int e = base; e < n_edges; e++) {
            out[e] = __ldg(&s1[src[e]]) + __ldg(&s2[dst[e]]) + b;
        }
    }
}

extern "C" void kernel_launch(void* const* d_in, const int* in_sizes, int n_in,
                              void* d_out, int out_size) {
    const float* x  = (const float*)d_in[0];   // (n_nodes, 128) f32
    const int*   ei = (const int*)d_in[1];     // (2, n_edges) int32
    const float* W  = (const float*)d_in[2];   // (1, 256) f32
    const float* b  = (const float*)d_in[3];   // (1,) f32
    float* out = (float*)d_out;

    int n_nodes = in_sizes[0] / HIDDEN;
    int n_edges = in_sizes[1] / 2;

    float* s1;
    float* s2;
    cudaGetSymbolAddress((void**)&s1, g_s1);
    cudaGetSymbolAddress((void**)&s2, g_s2);

    // Kernel 1: 2 nodes per warp (measured best: 9.4 us)
    {
        int threads = 256;                          // 8 warps/block
        int nodes_per_block = (threads / 32) * 2;   // 16
        int blocks = (n_nodes + nodes_per_block - 1) / nodes_per_block;
        node_dot_kernel<<<blocks, threads>>>((const float4*)x, (const float4*)W,
                                             n_nodes, s1, s2);
    }

    // Kernel 2: 4 edges/thread, 128-thread blocks (measured best: 10.37 us)
    {
        int threads = 128;
        int edges_per_block = threads * 4;
        int blocks = (n_edges + edges_per_block - 1) / edges_per_block;
        edge_kernel<<<blocks, threads>>>(ei, n_edges, s1, s2, b, out);
    }
}

// round 12
// speedup vs baseline: 1.4042x; 1.4042x over previous
#include <cuda_runtime.h>
#include <cuda_bf16.h>

#define HIDDEN 128
#define MAX_NODES 131072

__device__ float g_s1[MAX_NODES];
__device__ float g_s2[MAX_NODES];

// Two nodes per warp: lane l loads x[2w][4l..] and x[2w+1][4l..] back-to-back
// (MLP=2), computes 4 partial dots, 4 independent shfl-reduction chains.
// (Measured-best node_dot shape: R5 config.)
__global__ __launch_bounds__(512)
void node_dot_kernel(const float4* __restrict__ x4,
                     const float4* __restrict__ W4,
                     int n_nodes,
                     float* __restrict__ s1,
                     float* __restrict__ s2) {
    int warp = (blockIdx.x * blockDim.x + threadIdx.x) >> 5;
    int lane = threadIdx.x & 31;
    int n0 = warp * 2;
    if (n0 >= n_nodes) return;

    float4 w1 = __ldg(&W4[lane]);        // W[0:128]   (L1/L2 resident)
    float4 w2 = __ldg(&W4[32 + lane]);   // W[128:256]

    // Front-batch both row loads
    const float4* p = x4 + (size_t)n0 * 32 + lane;
    float4 v0 = p[0];
    float4 v1;
    bool has1 = (n0 + 1) < n_nodes;
    if (has1) v1 = p[32];

    float a0 = v0.x * w1.x + v0.y * w1.y + v0.z * w1.z + v0.w * w1.w;
    float c0 = v0.x * w2.x + v0.y * w2.y + v0.z * w2.z + v0.w * w2.w;
    float a1 = 0.f, c1 = 0.f;
    if (has1) {
        a1 = v1.x * w1.x + v1.y * w1.y + v1.z * w1.z + v1.w * w1.w;
        c1 = v1.x * w2.x + v1.y * w2.y + v1.z * w2.z + v1.w * w2.w;
    }

    #pragma unroll
    for (int o = 16; o > 0; o >>= 1) {
        a0 += __shfl_xor_sync(0xFFFFFFFFu, a0, o);
        c0 += __shfl_xor_sync(0xFFFFFFFFu, c0, o);
        a1 += __shfl_xor_sync(0xFFFFFFFFu, a1, o);
        c1 += __shfl_xor_sync(0xFFFFFFFFu, c1, o);
    }
    if (lane == 0) {
        s1[n0] = a0;
        s2[n0] = c0;
        if (has1) {
            s1[n0 + 1] = a1;
            s2[n0 + 1] = c1;
        }
    }
}

// out[e] = s1[src[e]] + s2[dst[e]] + b.
// Measured-best edge shape (reproduced twice at 10.37us): 4 edges/thread,
// int4 index loads, 8 front-batched gathers, 128-thread blocks.
__global__ __launch_bounds__(128)
void edge_kernel(const int* __restrict__ ei,
                 int n_edges,
                 const float* __restrict__ s1,
                 const float* __restrict__ s2,
                 const float* __restrict__ bptr,
                 float* __restrict__ out) {
    float b = __ldg(bptr);
    int tid = blockIdx.x * blockDim.x + threadIdx.x;
    int base = tid * 4;
    const int* src = ei;
    const int* dst = ei + n_edges;

    if (base + 3 < n_edges) {
        int4 s4 = __ldg((const int4*)(src + base));
        int4 d4 = __ldg((const int4*)(dst + base));

        float v0 = __ldg(&s1[s4.x]);
        float v1 = __ldg(&s1[s4.y]);
        float v2 = __ldg(&s1[s4.z]);
        float v3 = __ldg(&s1[s4.w]);
        float u0 = __ldg(&s2[d4.x]);
        float u1 = __ldg(&s2[d4.y]);
        float u2 = __ldg(&s2[d4.z]);
        float u3 = __ldg(&s2[d4.w]);

        float4 r = make_float4(v0 + u0 + b, v1 + u1 + b,
                               v2 + u2 + b, v3 + u3 + b);
        *(float4*)(out + base) = r;
    } else {
        for (int e = base; e < n_edges; e++) {
            out[e] = __ldg(&s1[src[e]]) + __ldg(&s2[dst[e]]) + b;
        }
    }
}

extern "C" void kernel_launch(void* const* d_in, const int* in_sizes, int n_in,
                              void* d_out, int out_size) {
    const float* x  = (const float*)d_in[0];   // (n_nodes, 128) f32
    const int*   ei = (const int*)d_in[1];     // (2, n_edges) int32
    const float* W  = (const float*)d_in[2];   // (1, 256) f32
    const float* b  = (const float*)d_in[3];   // (1,) f32
    float* out = (float*)d_out;

    int n_nodes = in_sizes[0] / HIDDEN;
    int n_edges = in_sizes[1] / 2;

    float* s1;
    float* s2;
    cudaGetSymbolAddress((void**)&s1, g_s1);
    cudaGetSymbolAddress((void**)&s2, g_s2);

    // Kernel 1: 2 nodes per warp (measured best shape)
    {
        int threads = 512;                          // 16 warps/block
        int nodes_per_block = (threads / 32) * 2;   // 32
        int blocks = (n_nodes + nodes_per_block - 1) / nodes_per_block;
        node_dot_kernel<<<blocks, threads>>>((const float4*)x, (const float4*)W,
                                             n_nodes, s1, s2);
    }

    // Kernel 2: 4 edges/thread, 128-thread blocks (measured best shape)
    {
        int threads = 128;
        int edges_per_block = threads * 4;
        int blocks = (n_edges + edges_per_block - 1) / edges_per_block;
        edge_kernel<<<blocks, threads>>>(ei, n_edges, s1, s2, b, out);
    }
}

// round 14
// speedup vs baseline: 1.4708x; 1.0474x over previous
#include <cuda_runtime.h>
#include <cuda_bf16.h>

#define HIDDEN 128
#define MAX_NODES 131072

__device__ float g_s1[MAX_NODES];
__device__ float g_s2[MAX_NODES];

// Two nodes per warp: lane l loads x[2w][4l..] and x[2w+1][4l..] back-to-back
// (MLP=2), computes 4 partial dots, 4 independent shfl-reduction chains.
// Exact R5 measured-best shape (9.4us), plus paired float2 result stores.
__global__ __launch_bounds__(256)
void node_dot_kernel(const float4* __restrict__ x4,
                     const float4* __restrict__ W4,
                     int n_nodes,
                     float* __restrict__ s1,
                     float* __restrict__ s2) {
    int warp = (blockIdx.x * blockDim.x + threadIdx.x) >> 5;
    int lane = threadIdx.x & 31;
    int n0 = warp * 2;
    if (n0 >= n_nodes) return;

    float4 w1 = W4[lane];        // W[0:128]   (L1/L2 resident)
    float4 w2 = W4[32 + lane];   // W[128:256]

    // Front-batch both row loads
    const float4* p = x4 + (size_t)n0 * 32 + lane;
    float4 v0 = p[0];
    float4 v1;
    bool has1 = (n0 + 1) < n_nodes;
    if (has1) v1 = p[32];

    float a0 = v0.x * w1.x + v0.y * w1.y + v0.z * w1.z + v0.w * w1.w;
    float c0 = v0.x * w2.x + v0.y * w2.y + v0.z * w2.z + v0.w * w2.w;
    float a1 = 0.f, c1 = 0.f;
    if (has1) {
        a1 = v1.x * w1.x + v1.y * w1.y + v1.z * w1.z + v1.w * w1.w;
        c1 = v1.x * w2.x + v1.y * w2.y + v1.z * w2.z + v1.w * w2.w;
    }

    #pragma unroll
    for (int o = 16; o > 0; o >>= 1) {
        a0 += __shfl_xor_sync(0xFFFFFFFFu, a0, o);
        c0 += __shfl_xor_sync(0xFFFFFFFFu, c0, o);
        a1 += __shfl_xor_sync(0xFFFFFFFFu, a1, o);
        c1 += __shfl_xor_sync(0xFFFFFFFFu, c1, o);
    }
    if (lane == 0) {
        if (has1) {
            // n0 is even -> 8B aligned: single STG.64 per array
            *(float2*)(s1 + n0) = make_float2(a0, a1);
            *(float2*)(s2 + n0) = make_float2(c0, c1);
        } else {
            s1[n0] = a0;
            s2[n0] = c0;
        }
    }
}

// out[e] = s1[src[e]] + s2[dst[e]] + b.
// Measured-best edge shape (3x reproduced at ~10.4us): 4 edges/thread,
// int4 index loads, 8 front-batched gathers, 128-thread blocks.
__global__ __launch_bounds__(128)
void edge_kernel(const int* __restrict__ ei,
                 int n_edges,
                 const float* __restrict__ s1,
                 const float* __restrict__ s2,
                 const float* __restrict__ bptr,
                 float* __restrict__ out) {
    float b = __ldg(bptr);
    int tid = blockIdx.x * blockDim.x + threadIdx.x;
    int base = tid * 4;
    const int* src = ei;
    const int* dst = ei + n_edges;

    if (base + 3 < n_edges) {
        int4 s4 = __ldg((const int4*)(src + base));
        int4 d4 = __ldg((const int4*)(dst + base));

        float v0 = __ldg(&s1[s4.x]);
        float v1 = __ldg(&s1[s4.y]);
        float v2 = __ldg(&s1[s4.z]);
        float v3 = __ldg(&s1[s4.w]);
        float u0 = __ldg(&s2[d4.x]);
        float u1 = __ldg(&s2[d4.y]);
        float u2 = __ldg(&s2[d4.z]);
        float u3 = __ldg(&s2[d4.w]);

        float4 r = make_float4(v0 + u0 + b, v1 + u1 + b,
                               v2 + u2 + b, v3 + u3 + b);
        *(float4*)(out + base) = r;
    } else {
        for (int e = base; e < n_edges; e++) {
            out[e] = __ldg(&s1[src[e]]) + __ldg(&s2[dst[e]]) + b;
        }
    }
}

extern "C" void kernel_launch(void* const* d_in, const int* in_sizes, int n_in,
                              void* d_out, int out_size) {
    const float* x  = (const float*)d_in[0];   // (n_nodes, 128) f32
    const int*   ei = (const int*)d_in[1];     // (2, n_edges) int32
    const float* W  = (const float*)d_in[2];   // (1, 256) f32
    const float* b  = (const float*)d_in[3];   // (1,) f32
    float* out = (float*)d_out;

    int n_nodes = in_sizes[0] / HIDDEN;
    int n_edges = in_sizes[1] / 2;

    float* s1;
    float* s2;
    cudaGetSymbolAddress((void**)&s1, g_s1);
    cudaGetSymbolAddress((void**)&s2, g_s2);

    // Kernel 1: 2 nodes per warp, 256-thread blocks (R5 measured best)
    {
        int threads = 256;                          // 8 warps/block
        int nodes_per_block = (threads / 32) * 2;   // 16
        int blocks = (n_nodes + nodes_per_block - 1) / nodes_per_block;
        node_dot_kernel<<<blocks, threads>>>((const float4*)x, (const float4*)W,
                                             n_nodes, s1, s2);
    }

    // Kernel 2: 4 edges/thread, 128-thread blocks (measured best)
    {
        int threads = 128;
        int edges_per_block = threads * 4;
        int blocks = (n_edges + edges_per_block - 1) / edges_per_block;
        edge_kernel<<<blocks, threads>>>(ei, n_edges, s1, s2, b, out);
    }
}